// round 15
// baseline (speedup 1.0000x reference)
#include <cuda_runtime.h>
#include <cuda_bf16.h>
#include <math.h>
#include <stdint.h>

#define BATCH 8
#define HB    4       // batch group size for pipelining
#define CH    1792
#define HW    3136
#define WCOLS 1794
#define KT64  28      // CH / 64
#define JSPLIT 3

// ---------------- scratch (device globals; no allocation APIs) ----------------
__device__ __align__(128) __nv_bfloat16 g_Wb [CH * CH];
__device__ __align__(128) __nv_bfloat16 g_x1t[BATCH * 3136 * 256];
__device__ __align__(128) __nv_bfloat16 g_x2t[BATCH * 784  * 512];
__device__ __align__(128) __nv_bfloat16 g_x3t[BATCH * 196  * 1024];
__device__ __align__(128) __nv_bfloat16 g_Ct [(HW + 256) * CH];          // padded
__device__ __align__(128) __nv_bfloat16 g_y1 [BATCH * CH * 3136];
__device__ __align__(128) __nv_bfloat16 g_y2 [BATCH * CH * 784];
__device__ __align__(128) __nv_bfloat16 g_y3 [BATCH * CH * 196];
__device__ __align__(128) __nv_bfloat16 g_q2 [BATCH * CH * 784];
__device__ __align__(128) __nv_bfloat16 g_q3 [BATCH * CH * 196];
__device__ __align__(128) __nv_bfloat16 g_phiT[(BATCH * HW + 256) * CH]; // padded
__device__ float g_rownp[KT64][BATCH * HW];
__device__ float g_rown[BATCH * HW];
__device__ float g_coln[HW];
__device__ float g_top3[BATCH * JSPLIT * HW * 3];

__device__ __forceinline__ void ins3(float &a0, float &a1, float &a2, float x)
{
    float o0 = fminf(a0, x);
    float o1 = fminf(a1, fmaxf(a0, x));
    float o2 = fminf(a2, fmaxf(a1, x));
    a0 = o0; a1 = o1; a2 = o2;
}

__device__ __forceinline__ uint32_t smem_u32(const void* p)
{
    uint32_t a;
    asm("{ .reg .u64 t; cvta.to.shared.u64 t, %1; cvt.u32.u64 %0, t; }"
        : "=r"(a) : "l"(p));
    return a;
}

__device__ __forceinline__ void ldsm4(uint32_t &r0, uint32_t &r1, uint32_t &r2,
                                      uint32_t &r3, uint32_t addr)
{
    asm volatile("ldmatrix.sync.aligned.m8n8.x4.shared.b16 {%0,%1,%2,%3}, [%4];"
                 : "=r"(r0), "=r"(r1), "=r"(r2), "=r"(r3) : "r"(addr));
}

__device__ __forceinline__ void mma16816(float c[4],
                                         uint32_t a0, uint32_t a1, uint32_t a2, uint32_t a3,
                                         uint32_t b0, uint32_t b1)
{
    asm volatile("mma.sync.aligned.m16n8k16.row.col.f32.bf16.bf16.f32 "
                 "{%0,%1,%2,%3}, {%4,%5,%6,%7}, {%8,%9}, {%0,%1,%2,%3};"
                 : "+f"(c[0]), "+f"(c[1]), "+f"(c[2]), "+f"(c[3])
                 : "r"(a0), "r"(a1), "r"(a2), "r"(a3), "r"(b0), "r"(b1));
}

__device__ __forceinline__ void cpa16(uint32_t dst, const void* src, int srcBytes)
{
    asm volatile("cp.async.cg.shared.global [%0], [%1], 16, %2;"
                 :: "r"(dst), "l"(src), "r"(srcBytes));
}
__device__ __forceinline__ void cpa_commit()
{
    asm volatile("cp.async.commit_group;");
}
template<int N> __device__ __forceinline__ void cpa_wait()
{
    asm volatile("cp.async.wait_group %0;" :: "n"(N));
}

// ============================================================================
// fp32 (P, R, S) -> bf16 (P, S, R) tiled transpose+convert
// ============================================================================
__global__ void transpose_conv(const float* __restrict__ in,
                               __nv_bfloat16* __restrict__ out, int R, int S)
{
    __shared__ float tile[32][33];
    int p = blockIdx.z;
    int s0 = blockIdx.x * 32, r0 = blockIdx.y * 32;
    const float* ip = in + (size_t)p * R * S;
    __nv_bfloat16* op = out + (size_t)p * R * S;
    int tx = threadIdx.x, ty = threadIdx.y;
#pragma unroll
    for (int dy = 0; dy < 32; dy += 8) {
        int r = r0 + ty + dy, s = s0 + tx;
        tile[ty + dy][tx] = (r < R && s < S) ? ip[(size_t)r * S + s] : 0.f;
    }
    __syncthreads();
#pragma unroll
    for (int dy = 0; dy < 32; dy += 8) {
        int s = s0 + ty + dy, r = r0 + tx;
        if (s < S && r < R) op[(size_t)s * R + r] = __float2bfloat16(tile[tx][ty + dy]);
    }
}

__global__ void conv_w(const float* __restrict__ W, __nv_bfloat16* __restrict__ Wb)
{
    int i = blockIdx.x * 256 + threadIdx.x;
    if (i >= CH * CH) return;
    int o = i / CH, c = i % CH;
    Wb[i] = __float2bfloat16(W[(size_t)o * WCOLS + c]);
}

// ============================================================================
// bf16 HMMA level GEMM: BK=64, 3-stage cp.async ring, ONE sync per chunk,
// SW128-swizzled 128-B rows, 2 CTAs/SM.
// ============================================================================
#define L6STG  32768u
#define L6B    16384u
#define L6SMEM (3 * 32768)

__global__ __launch_bounds__(256, 2)
void level_mma2(const __nv_bfloat16* __restrict__ Xt,
                __nv_bfloat16* __restrict__ Y, int K, int Nloc, int woff)
{
    extern __shared__ __align__(128) char lsm[];
    const uint32_t smb = smem_u32(lsm);

    const int n0 = blockIdx.x * 128;
    const int m0 = blockIdx.y * 128;
    const int b  = blockIdx.z;
    const __nv_bfloat16* Xb = Xt + (size_t)b * Nloc * K;

    const int tid = threadIdx.x;
    const int lane = tid & 31, w = tid >> 5;
    const int wr = w >> 2, wc = w & 3;
    const int g = lane >> 2, tg = lane & 3;

    const int lr = tid >> 1, lv = tid & 1;
    const __nv_bfloat16* aRow = g_Wb + (size_t)(m0 + lr) * CH + woff + lv * 32;
    const int jB = n0 + lr;
    const __nv_bfloat16* bRow =
        Xb + (size_t)(jB < Nloc ? jB : Nloc - 1) * K + lv * 32;
    const int bvld = (jB < Nloc) ? 16 : 0;
    uint32_t wsw[4];
#pragma unroll
    for (int c = 0; c < 4; c++)
        wsw[c] = (uint32_t)((lv * 64 + c * 16) ^ ((lr & 7) << 4));
    const uint32_t aWrRow = smb + (uint32_t)(lr * 128);
    const uint32_t bWrRow = smb + L6B + (uint32_t)(lr * 128);

    uint32_t aswc[4], bswc[4];
#pragma unroll
    for (int s = 0; s < 4; s++) {
        aswc[s] = (uint32_t)((((lane >> 4) * 16) + s * 32) ^ ((lane & 7) << 4));
        bswc[s] = (uint32_t)(((((lane >> 3) & 1) * 16) + s * 32) ^ ((lane & 7) << 4));
    }
    const uint32_t aRowBase = smb + (uint32_t)(((wr * 64) + (lane & 15)) * 128);
    const uint32_t bRowBase = smb + L6B +
        (uint32_t)((wc * 32 + (lane & 7) + ((lane >> 4) & 1) * 8) * 128);

    float acc[4][4][4];
#pragma unroll
    for (int mi = 0; mi < 4; mi++)
#pragma unroll
        for (int ni = 0; ni < 4; ni++)
#pragma unroll
            for (int q = 0; q < 4; q++) acc[mi][ni][q] = 0.f;

    const int KT = K / 64;
#pragma unroll
    for (int p = 0; p < 2; p++) {
#pragma unroll
        for (int c = 0; c < 4; c++) {
            cpa16(aWrRow + p * L6STG + wsw[c], aRow + p * 64 + c * 8, 16);
            cpa16(bWrRow + p * L6STG + wsw[c], bRow + p * 64 + c * 8, bvld);
        }
        cpa_commit();
    }

    for (int kc = 0; kc < KT; kc++) {
        if (kc < KT - 1) cpa_wait<1>(); else cpa_wait<0>();
        __syncthreads();
        const int kl = kc + 2;
        if (kl < KT) {
            const uint32_t so = (uint32_t)(kl % 3) * L6STG;
#pragma unroll
            for (int c = 0; c < 4; c++) {
                cpa16(aWrRow + so + wsw[c], aRow + kl * 64 + c * 8, 16);
                cpa16(bWrRow + so + wsw[c], bRow + kl * 64 + c * 8, bvld);
            }
            cpa_commit();
        }
        const uint32_t stg = (uint32_t)(kc % 3) * L6STG;
#pragma unroll
        for (int s = 0; s < 4; s++) {
            uint32_t bq[8];
            ldsm4(bq[0], bq[1], bq[2], bq[3], bRowBase + stg + bswc[s]);
            ldsm4(bq[4], bq[5], bq[6], bq[7], bRowBase + stg + 16 * 128 + bswc[s]);
#pragma unroll
            for (int mi = 0; mi < 4; mi++) {
                uint32_t a0, a1, a2, a3;
                ldsm4(a0, a1, a2, a3, aRowBase + stg + mi * 16 * 128 + aswc[s]);
#pragma unroll
                for (int ni = 0; ni < 4; ni++)
                    mma16816(acc[mi][ni], a0, a1, a2, a3, bq[ni * 2], bq[ni * 2 + 1]);
            }
        }
    }

    __nv_bfloat16* Yb = Y + (size_t)b * CH * Nloc;
#pragma unroll
    for (int mi = 0; mi < 4; mi++) {
        int r = m0 + wr * 64 + mi * 16 + g;
#pragma unroll
        for (int ni = 0; ni < 4; ni++) {
            int ccol = n0 + wc * 32 + ni * 8 + 2 * tg;
            if (ccol < Nloc) {
                *reinterpret_cast<__nv_bfloat162*>(&Yb[(size_t)r * Nloc + ccol]) =
                    __floats2bfloat162_rn(acc[mi][ni][0], acc[mi][ni][1]);
                *reinterpret_cast<__nv_bfloat162*>(&Yb[(size_t)(r + 8) * Nloc + ccol]) =
                    __floats2bfloat162_rn(acc[mi][ni][2], acc[mi][ni][3]);
            }
        }
    }
}

// ============================================================================
// Vectorized 3x3 avg pool (zero pad, /9): 4 outputs/thread via bf16x2 loads.
// ============================================================================
template<int S>
__global__ void pool4(const __nv_bfloat16* __restrict__ in,
                      __nv_bfloat16* __restrict__ out, int total4)
{
    constexpr int G = S / 4;
    int idx = blockIdx.x * blockDim.x + threadIdx.x;
    if (idx >= total4) return;
    int gw = idx % G;
    int h  = (idx / G) % S;
    int plane = idx / (G * S);
    int w0 = gw * 4;
    const __nv_bfloat16* ip = in + (size_t)plane * S * S;

    float cs0 = 0.f, cs1 = 0.f, cs2 = 0.f, cs3 = 0.f, cs4 = 0.f, cs5 = 0.f;
#pragma unroll
    for (int dh = -1; dh <= 1; dh++) {
        int hh = h + dh;
        if (hh < 0 || hh >= S) continue;
        const __nv_bfloat16* rp = ip + hh * S;
        if (w0 > 0) {
            __nv_bfloat162 a = *reinterpret_cast<const __nv_bfloat162*>(rp + w0 - 2);
            cs0 += __bfloat162float(a.y);
        }
        __nv_bfloat162 bvv = *reinterpret_cast<const __nv_bfloat162*>(rp + w0);
        cs1 += __bfloat162float(bvv.x);
        cs2 += __bfloat162float(bvv.y);
        __nv_bfloat162 cvv = *reinterpret_cast<const __nv_bfloat162*>(rp + w0 + 2);
        cs3 += __bfloat162float(cvv.x);
        cs4 += __bfloat162float(cvv.y);
        if (w0 + 4 < S) {
            __nv_bfloat162 dvv = *reinterpret_cast<const __nv_bfloat162*>(rp + w0 + 4);
            cs5 += __bfloat162float(dvv.x);
        }
    }
    const float inv9 = 1.f / 9.f;
    float o0 = (cs0 + cs1 + cs2) * inv9;
    float o1 = (cs1 + cs2 + cs3) * inv9;
    float o2 = (cs2 + cs3 + cs4) * inv9;
    float o3 = (cs3 + cs4 + cs5) * inv9;
    __nv_bfloat162 v0 = __floats2bfloat162_rn(o0, o1);
    __nv_bfloat162 v1 = __floats2bfloat162_rn(o2, o3);
    uint2 pk = make_uint2(*reinterpret_cast<uint32_t*>(&v0),
                          *reinterpret_cast<uint32_t*>(&v1));
    *reinterpret_cast<uint2*>(out + (size_t)plane * S * S + h * S + w0) = pk;
}

// scalar pool for S=14
template<int S>
__global__ void pool3b(const __nv_bfloat16* __restrict__ in,
                       __nv_bfloat16* __restrict__ out, int total)
{
    int idx = blockIdx.x * blockDim.x + threadIdx.x;
    if (idx >= total) return;
    int w = idx % S;
    int h = (idx / S) % S;
    const __nv_bfloat16* ip = in + (idx - h * S - w);
    float s = 0.f;
#pragma unroll
    for (int dh = -1; dh <= 1; dh++) {
        int hh = h + dh;
        if (hh < 0 || hh >= S) continue;
#pragma unroll
        for (int dw = -1; dw <= 1; dw++) {
            int ww = w + dw;
            if (ww < 0 || ww >= S) continue;
            s += __bfloat162float(ip[hh * S + ww]);
        }
    }
    out[idx] = __float2bfloat16(s * (1.f / 9.f));
}

// ============================================================================
// Fused assemble: inline 3x3 pool of y1 + up2(q2) + up4(q3) + coords + bias
// -> bf16 phiT (b, i, k) + row-norm partials (batch group)
// ============================================================================
__global__ __launch_bounds__(256)
void assemble_t(const float* __restrict__ Wmat, const float* __restrict__ bvec,
                int b0)
{
    __shared__ float tile[64][65];
    __shared__ float rsum[4][64];
    const int i0 = blockIdx.x * 64;
    const int kt = blockIdx.y;
    const int k0 = kt * 64;
    const int b  = b0 + blockIdx.z;
    const int tx = threadIdx.x;
    const int ty = threadIdx.y;
    const int i  = i0 + tx;
    const int h = i / 56, w = i % 56;

    // 3x3 pool window of y1 (zero pad -> just skip invalid, /9)
    int poff[9];
    int np = 0;
#pragma unroll
    for (int dh = -1; dh <= 1; dh++) {
        int hh = h + dh;
        if (hh < 0 || hh >= 56) continue;
#pragma unroll
        for (int dw = -1; dw <= 1; dw++) {
            int ww = w + dw;
            if (ww < 0 || ww >= 56) continue;
            poff[np++] = hh * 56 + ww;
        }
    }

    float w2[4]; int o2[4];
    {
        float cy = (h + 0.5f) * 0.5f - 0.5f;
        float cx = (w + 0.5f) * 0.5f - 0.5f;
        float fy0 = floorf(cy), fx0 = floorf(cx);
        float fy = cy - fy0, fx = cx - fx0;
        int y0 = max((int)fy0, 0), y1 = min((int)fy0 + 1, 27);
        int x0 = max((int)fx0, 0), x1 = min((int)fx0 + 1, 27);
        o2[0] = y0 * 28 + x0; o2[1] = y0 * 28 + x1;
        o2[2] = y1 * 28 + x0; o2[3] = y1 * 28 + x1;
        w2[0] = (1.f - fy) * (1.f - fx); w2[1] = (1.f - fy) * fx;
        w2[2] = fy * (1.f - fx);         w2[3] = fy * fx;
    }
    float w3[4]; int o3[4];
    {
        float cy = (h + 0.5f) * 0.25f - 0.5f;
        float cx = (w + 0.5f) * 0.25f - 0.5f;
        float fy0 = floorf(cy), fx0 = floorf(cx);
        float fy = cy - fy0, fx = cx - fx0;
        int y0 = max((int)fy0, 0), y1 = min((int)fy0 + 1, 13);
        int x0 = max((int)fx0, 0), x1 = min((int)fx0 + 1, 13);
        o3[0] = y0 * 14 + x0; o3[1] = y0 * 14 + x1;
        o3[2] = y1 * 14 + x0; o3[3] = y1 * 14 + x1;
        w3[0] = (1.f - fy) * (1.f - fx); w3[1] = (1.f - fy) * fx;
        w3[2] = fy * (1.f - fx);         w3[3] = fy * fx;
    }
    const float xx = fmaf(2.f / 55.f, (float)w, -1.f);
    const float yy = fmaf(2.f / 55.f, (float)h, -1.f);

    float s = 0.f;
    for (int r = ty; r < 64; r += 4) {
        const int k = k0 + r;
        const size_t pk = (size_t)b * CH + k;
        const __nv_bfloat16* pl1 = g_y1 + pk * 3136;
        float v = 0.f;
        for (int j = 0; j < np; j++)
            v += __bfloat162float(pl1[poff[j]]);
        v *= (1.f / 9.f);
        const __nv_bfloat16* pl2 = g_q2 + pk * 784;
        const __nv_bfloat16* pl3 = g_q3 + pk * 196;
        v += w2[0] * __bfloat162float(pl2[o2[0]]) + w2[1] * __bfloat162float(pl2[o2[1]])
           + w2[2] * __bfloat162float(pl2[o2[2]]) + w2[3] * __bfloat162float(pl2[o2[3]]);
        v += w3[0] * __bfloat162float(pl3[o3[0]]) + w3[1] * __bfloat162float(pl3[o3[1]])
           + w3[2] * __bfloat162float(pl3[o3[2]]) + w3[3] * __bfloat162float(pl3[o3[3]]);
        v += Wmat[(size_t)k * WCOLS + 1792] * xx
           + Wmat[(size_t)k * WCOLS + 1793] * yy
           + bvec[k];
        float fq = __bfloat162float(__float2bfloat16(v));
        tile[r][tx] = fq;
        s = fmaf(fq, fq, s);
    }
    rsum[ty][tx] = s;
    __syncthreads();
    if (ty == 0)
        g_rownp[kt][b * HW + i] = rsum[0][tx] + rsum[1][tx] + rsum[2][tx] + rsum[3][tx];
#pragma unroll
    for (int q = 0; q < 16; q++) {
        int ri = ty + q * 4;
        g_phiT[((size_t)b * HW + (i0 + ri)) * CH + k0 + tx] =
            __float2bfloat16(tile[tx][ri]);
    }
}

__global__ void reduce_rown(int b0)
{
    int idx = blockIdx.x * 256 + threadIdx.x;
    if (idx >= HB * HW) return;
    idx += b0 * HW;
    float s = 0.f;
#pragma unroll
    for (int q = 0; q < KT64; q++) s += g_rownp[q][idx];
    g_rown[idx] = s;
}

__global__ void col_norms_b()
{
    int gw = (blockIdx.x * 256 + threadIdx.x) >> 5;
    int lane = threadIdx.x & 31;
    if (gw >= HW) return;
    const __nv_bfloat16* row = g_Ct + (size_t)gw * CH;
    float s = 0.f;
    for (int k = lane; k < CH; k += 32) {
        float v = __bfloat162float(row[k]);
        s = fmaf(v, v, s);
    }
#pragma unroll
    for (int m = 16; m; m >>= 1) s += __shfl_xor_sync(0xffffffffu, s, m);
    if (lane == 0) g_coln[gw] = s;
}

// ============================================================================
// Fused distance GEMM (HMMA, 128x128, 256 thr, 8 warps 2x4, warp tile 64x32):
// BK=64, 3-stage cp.async ring, ONE __syncthreads per 64-k chunk,
// SW128-swizzled 128-B smem rows, 2 CTAs/SM. Grid (25, HB, JSPLIT).
// ============================================================================
#define D6STG  32768u
#define D6B    16384u
#define D6RED  (3 * 32768)
#define D6SMEM (D6RED + 4 * 128 * 3 * 4)

__global__ __launch_bounds__(256, 2)
void dist_mma6(int b0)
{
    extern __shared__ __align__(128) char dsm[];
    const uint32_t smb = smem_u32(dsm);
    float* red = reinterpret_cast<float*>(dsm + D6RED);

    const int tid = threadIdx.x;
    const int lane = tid & 31, w = tid >> 5;
    const int wr = w >> 2, wc = w & 3;
    const int g = lane >> 2, tg = lane & 3;
    const int m0 = blockIdx.x * 128;
    const int b  = b0 + blockIdx.y;
    const int js = blockIdx.z;
    const int jt0 = (js * 25) / JSPLIT;
    const int jt1 = ((js + 1) * 25) / JSPLIT;

    const int lr = tid >> 1, lv = tid & 1;
    const int iA = m0 + lr;
    const __nv_bfloat16* aRow =
        g_phiT + ((size_t)b * HW + (iA < HW ? iA : HW - 1)) * CH + lv * 32;
    const int avld = (iA < HW) ? 16 : 0;
    uint32_t wsw[4];
#pragma unroll
    for (int c = 0; c < 4; c++)
        wsw[c] = (uint32_t)((lv * 64 + c * 16) ^ ((lr & 7) << 4));
    const uint32_t aWrRow = smb + (uint32_t)(lr * 128);
    const uint32_t bWrRow = smb + D6B + (uint32_t)(lr * 128);

    uint32_t aswc[4], bswc[4];
#pragma unroll
    for (int s = 0; s < 4; s++) {
        aswc[s] = (uint32_t)((((lane >> 4) * 16) + s * 32) ^ ((lane & 7) << 4));
        bswc[s] = (uint32_t)(((((lane >> 3) & 1) * 16) + s * 32) ^ ((lane & 7) << 4));
    }
    const uint32_t aRowBase = smb + (uint32_t)(((wr * 64) + (lane & 15)) * 128);
    const uint32_t bRowBase = smb + D6B +
        (uint32_t)((wc * 32 + (lane & 7) + ((lane >> 4) & 1) * 8) * 128);

    float nr[4][2];
    float t0[4][2], t1[4][2], t2[4][2];
#pragma unroll
    for (int mi = 0; mi < 4; mi++)
#pragma unroll
        for (int hh = 0; hh < 2; hh++) {
            int r = m0 + wr * 64 + mi * 16 + g + hh * 8;
            nr[mi][hh] = (r < HW) ? g_rown[b * HW + r] : 0.f;
            t0[mi][hh] = INFINITY; t1[mi][hh] = INFINITY; t2[mi][hh] = INFINITY;
        }

    for (int jt = jt0; jt < jt1; jt++) {
        const int n0 = jt * 128;
        const __nv_bfloat16* bRow = g_Ct + (size_t)(n0 + lr) * CH + lv * 32;

        float acc[4][4][4];
#pragma unroll
        for (int mi = 0; mi < 4; mi++)
#pragma unroll
            for (int ni = 0; ni < 4; ni++)
#pragma unroll
                for (int q = 0; q < 4; q++) acc[mi][ni][q] = 0.f;

        __syncthreads();
#pragma unroll
        for (int p = 0; p < 2; p++) {
#pragma unroll
            for (int c = 0; c < 4; c++) {
                cpa16(aWrRow + p * D6STG + wsw[c], aRow + p * 64 + c * 8, avld);
                cpa16(bWrRow + p * D6STG + wsw[c], bRow + p * 64 + c * 8, 16);
            }
            cpa_commit();
        }

        for (int kc = 0; kc < KT64; kc++) {
            if (kc < KT64 - 1) cpa_wait<1>(); else cpa_wait<0>();
            __syncthreads();
            const int kl = kc + 2;
            if (kl < KT64) {
                const uint32_t so = (uint32_t)(kl % 3) * D6STG;
#pragma unroll
                for (int c = 0; c < 4; c++) {
                    cpa16(aWrRow + so + wsw[c], aRow + kl * 64 + c * 8, avld);
                    cpa16(bWrRow + so + wsw[c], bRow + kl * 64 + c * 8, 16);
                }
                cpa_commit();
            }
            const uint32_t stg = (uint32_t)(kc % 3) * D6STG;
#pragma unroll
            for (int s = 0; s < 4; s++) {
                uint32_t bq[8];
                ldsm4(bq[0], bq[1], bq[2], bq[3], bRowBase + stg + bswc[s]);
                ldsm4(bq[4], bq[5], bq[6], bq[7], bRowBase + stg + 16 * 128 + bswc[s]);
#pragma unroll
                for (int mi = 0; mi < 4; mi++) {
                    uint32_t a0, a1, a2, a3;
                    ldsm4(a0, a1, a2, a3, aRowBase + stg + mi * 16 * 128 + aswc[s]);
#pragma unroll
                    for (int ni = 0; ni < 4; ni++)
                        mma16816(acc[mi][ni], a0, a1, a2, a3, bq[ni * 2], bq[ni * 2 + 1]);
                }
            }
        }

#pragma unroll
        for (int ni = 0; ni < 4; ni++) {
            int col0 = n0 + wc * 32 + ni * 8 + 2 * tg;
            if (col0 < HW) {
                float mj0 = g_coln[col0];
                float mj1 = g_coln[col0 + 1];
#pragma unroll
                for (int mi = 0; mi < 4; mi++) {
#pragma unroll
                    for (int hh = 0; hh < 2; hh++) {
                        float base = nr[mi][hh];
                        float d0 = fmaf(-2.f, acc[mi][ni][hh * 2],     base + mj0);
                        float d1 = fmaf(-2.f, acc[mi][ni][hh * 2 + 1], base + mj1);
                        ins3(t0[mi][hh], t1[mi][hh], t2[mi][hh], d0);
                        ins3(t0[mi][hh], t1[mi][hh], t2[mi][hh], d1);
                    }
                }
            }
        }
    }

#pragma unroll
    for (int msk = 1; msk < 4; msk <<= 1) {
#pragma unroll
        for (int mi = 0; mi < 4; mi++)
#pragma unroll
            for (int hh = 0; hh < 2; hh++) {
                float b0s = __shfl_xor_sync(0xffffffffu, t0[mi][hh], msk);
                float b1s = __shfl_xor_sync(0xffffffffu, t1[mi][hh], msk);
                float b2s = __shfl_xor_sync(0xffffffffu, t2[mi][hh], msk);
                ins3(t0[mi][hh], t1[mi][hh], t2[mi][hh], b0s);
                ins3(t0[mi][hh], t1[mi][hh], t2[mi][hh], b1s);
                ins3(t0[mi][hh], t1[mi][hh], t2[mi][hh], b2s);
            }
    }
    __syncthreads();
    if (tg == 0) {
#pragma unroll
        for (int mi = 0; mi < 4; mi++)
#pragma unroll
            for (int hh = 0; hh < 2; hh++) {
                int rl = wr * 64 + mi * 16 + g + hh * 8;
                float* rp = red + (wc * 128 + rl) * 3;
                rp[0] = t0[mi][hh];
                rp[1] = t1[mi][hh];
                rp[2] = t2[mi][hh];
            }
    }
    __syncthreads();
    if (tid < 128) {
        int ig = m0 + tid;
        if (ig < HW) {
            float a0 = INFINITY, a1 = INFINITY, a2 = INFINITY;
#pragma unroll
            for (int wcx = 0; wcx < 4; wcx++) {
                const float* rp = red + (wcx * 128 + tid) * 3;
                ins3(a0, a1, a2, rp[0]);
                ins3(a0, a1, a2, rp[1]);
                ins3(a0, a1, a2, rp[2]);
            }
            size_t base = (((size_t)b * JSPLIT + js) * HW + ig) * 3;
            g_top3[base + 0] = a0;
            g_top3[base + 1] = a1;
            g_top3[base + 2] = a2;
        }
    }
}

__global__ void finalize(float* __restrict__ out)
{
    int idx = blockIdx.x * blockDim.x + threadIdx.x;
    if (idx >= BATCH * HW) return;
    int b = idx / HW;
    int i = idx % HW;
    float t0 = INFINITY, t1 = INFINITY, t2 = INFINITY;
#pragma unroll
    for (int js = 0; js < JSPLIT; js++) {
        size_t base = (((size_t)b * JSPLIT + js) * HW + i) * 3;
        ins3(t0, t1, t2, g_top3[base + 0]);
        ins3(t0, t1, t2, g_top3[base + 1]);
        ins3(t0, t1, t2, g_top3[base + 2]);
    }
    float d0 = sqrtf(fmaxf(t0, 0.f));
    float d1 = sqrtf(fmaxf(t1, 0.f));
    float d2 = sqrtf(fmaxf(t2, 0.f));
    float w0 = 1.f / (1.f + expf(d0 - d1) + expf(d0 - d2));
    out[idx] = w0 * d0;
}

// ============================================================================
extern "C" void kernel_launch(void* const* d_in, const int* in_sizes, int n_in,
                              void* d_out, int out_size)
{
    const float *p1 = nullptr, *p2 = nullptr, *p3 = nullptr;
    const float *W = nullptr, *bv = nullptr, *Cm = nullptr;
    for (int i = 0; i < n_in; i++) {
        switch (in_sizes[i]) {
            case 8 * 256 * 56 * 56:  p1 = (const float*)d_in[i]; break;
            case 8 * 512 * 28 * 28:  p2 = (const float*)d_in[i]; break;
            case 8 * 1024 * 14 * 14: p3 = (const float*)d_in[i]; break;
            case 1792 * 1794:        W  = (const float*)d_in[i]; break;
            case 1792:               bv = (const float*)d_in[i]; break;
            case 1792 * 3136:        Cm = (const float*)d_in[i]; break;
            default: break;
        }
    }

    void *wb, *x1t, *x2t, *x3t, *ct;
    void *y1, *y2, *y3, *q2, *q3;
    cudaGetSymbolAddress(&wb,  g_Wb);
    cudaGetSymbolAddress(&x1t, g_x1t);
    cudaGetSymbolAddress(&x2t, g_x2t);
    cudaGetSymbolAddress(&x3t, g_x3t);
    cudaGetSymbolAddress(&ct,  g_Ct);
    cudaGetSymbolAddress(&y1,  g_y1);
    cudaGetSymbolAddress(&y2,  g_y2);  cudaGetSymbolAddress(&q2, g_q2);
    cudaGetSymbolAddress(&y3,  g_y3);  cudaGetSymbolAddress(&q3, g_q3);

    // one-time host-side resources (no device memory involved)
    static cudaStream_t s1 = nullptr, s2 = nullptr, s3 = nullptr;
    static cudaEvent_t eF, e0, e1, e2, e3, eM, eA, eG1;
    if (!s1) {
        cudaStreamCreateWithFlags(&s1, cudaStreamNonBlocking);
        cudaStreamCreateWithFlags(&s2, cudaStreamNonBlocking);
        cudaStreamCreateWithFlags(&s3, cudaStreamNonBlocking);
        cudaEventCreateWithFlags(&eF,  cudaEventDisableTiming);
        cudaEventCreateWithFlags(&e0,  cudaEventDisableTiming);
        cudaEventCreateWithFlags(&e1,  cudaEventDisableTiming);
        cudaEventCreateWithFlags(&e2,  cudaEventDisableTiming);
        cudaEventCreateWithFlags(&e3,  cudaEventDisableTiming);
        cudaEventCreateWithFlags(&eM,  cudaEventDisableTiming);
        cudaEventCreateWithFlags(&eA,  cudaEventDisableTiming);
        cudaEventCreateWithFlags(&eG1, cudaEventDisableTiming);
        cudaFuncSetAttribute(dist_mma6,
                             cudaFuncAttributeMaxDynamicSharedMemorySize, D6SMEM);
        cudaFuncSetAttribute(level_mma2,
                             cudaFuncAttributeMaxDynamicSharedMemorySize, L6SMEM);
    }

    dim3 tb(32, 8);

    // fork event FIRST (capture legality), then independent transposes
    cudaEventRecord(eF, 0);
    cudaStreamWaitEvent(s1, eF, 0);
    cudaStreamWaitEvent(s2, eF, 0);
    cudaStreamWaitEvent(s3, eF, 0);

    transpose_conv<<<dim3(25, 16, 8), tb, 0, s1>>>(p2, (__nv_bfloat16*)x2t, 512, 784);
    transpose_conv<<<dim3(7, 32, 8), tb, 0, s2>>>(p3, (__nv_bfloat16*)x3t, 1024, 196);
    transpose_conv<<<dim3(98, 56, 1), tb, 0, s3>>>(Cm, (__nv_bfloat16*)ct, 1792, 3136);
    col_norms_b<<<(HW * 32 + 255) / 256, 256, 0, s3>>>();
    cudaEventRecord(e3, s3);

    // main: Wb conversion (gates the level GEMMs), then level-1 chain (no pool!)
    conv_w<<<(CH * CH + 255) / 256, 256>>>(W, (__nv_bfloat16*)wb);
    cudaEventRecord(e0, 0);
    cudaStreamWaitEvent(s1, e0, 0);
    cudaStreamWaitEvent(s2, e0, 0);

    transpose_conv<<<dim3(98, 8, 8), tb>>>(p1, (__nv_bfloat16*)x1t, 256, 3136);
    level_mma2<<<dim3(25, 14, 8), 256, L6SMEM>>>((const __nv_bfloat16*)x1t,
                                                 (__nv_bfloat16*)y1, 256, 3136, 0);
    cudaEventRecord(eM, 0);

    // s1: level-2 chain
    level_mma2<<<dim3(7, 14, 8), 256, L6SMEM, s1>>>((const __nv_bfloat16*)x2t,
                                                    (__nv_bfloat16*)y2, 512, 784, 256);
    pool4<28><<<(BATCH * CH * 784 / 4 + 255) / 256, 256, 0, s1>>>(
        (const __nv_bfloat16*)y2, (__nv_bfloat16*)q2, BATCH * CH * 784 / 4);
    cudaEventRecord(e1, s1);

    // s2: level-3 chain
    level_mma2<<<dim3(2, 14, 8), 256, L6SMEM, s2>>>((const __nv_bfloat16*)x3t,
                                                    (__nv_bfloat16*)y3, 1024, 196, 768);
    pool3b<14><<<(BATCH * CH * 196 + 255) / 256, 256, 0, s2>>>(
        (const __nv_bfloat16*)y3, (__nv_bfloat16*)q3, BATCH * CH * 196);
    cudaEventRecord(e2, s2);

    // ---- group 0 (batches 0..3) on main; group 1 (4..7) on s1, staggered ----
    cudaStreamWaitEvent(0, e1, 0);
    cudaStreamWaitEvent(0, e2, 0);
    cudaStreamWaitEvent(0, e3, 0);

    assemble_t<<<dim3(49, 28, HB), dim3(64, 4)>>>(W, bv, 0);
    reduce_rown<<<(HB * HW + 255) / 256, 256>>>(0);
    cudaEventRecord(eA, 0);

    // s1 runs group 1 after group 0's assemble (overlaps with dist_g0)
    cudaStreamWaitEvent(s1, eM, 0);
    cudaStreamWaitEvent(s1, e2, 0);
    cudaStreamWaitEvent(s1, e3, 0);
    cudaStreamWaitEvent(s1, eA, 0);
    assemble_t<<<dim3(49, 28, HB), dim3(64, 4), 0, s1>>>(W, bv, HB);
    reduce_rown<<<(HB * HW + 255) / 256, 256, 0, s1>>>(HB);
    dist_mma6<<<dim3(25, HB, JSPLIT), 256, D6SMEM, s1>>>(HB);
    cudaEventRecord(eG1, s1);

    dist_mma6<<<dim3(25, HB, JSPLIT), 256, D6SMEM>>>(0);

    cudaStreamWaitEvent(0, eG1, 0);
    finalize<<<(BATCH * HW + 255) / 256, 256>>>((float*)d_out);
}

// round 16
// speedup vs baseline: 1.0961x; 1.0961x over previous
#include <cuda_runtime.h>
#include <cuda_bf16.h>
#include <math.h>
#include <stdint.h>

#define BATCH 8
#define HB    4       // batch group size for pipelining
#define CH    1792
#define HW    3136
#define WCOLS 1794
#define KT64  28      // CH / 64
#define JSPLIT 3

// ---------------- scratch (device globals; no allocation APIs) ----------------
__device__ __align__(128) __nv_bfloat16 g_Wb [CH * CH];
__device__ __align__(128) __nv_bfloat16 g_x1t[BATCH * 3136 * 256];
__device__ __align__(128) __nv_bfloat16 g_x2t[BATCH * 784  * 512];
__device__ __align__(128) __nv_bfloat16 g_x3t[BATCH * 196  * 1024];
__device__ __align__(128) __nv_bfloat16 g_Ct [(HW + 256) * CH];          // padded
__device__ __align__(128) __nv_bfloat16 g_y1 [BATCH * CH * 3136];
__device__ __align__(128) __nv_bfloat16 g_y2 [BATCH * CH * 784];
__device__ __align__(128) __nv_bfloat16 g_y3 [BATCH * CH * 196];
__device__ __align__(128) __nv_bfloat16 g_q1 [BATCH * CH * 3136];
__device__ __align__(128) __nv_bfloat16 g_q2 [BATCH * CH * 784];
__device__ __align__(128) __nv_bfloat16 g_q3 [BATCH * CH * 196];
__device__ __align__(128) __nv_bfloat16 g_phiT[(BATCH * HW + 256) * CH]; // padded
__device__ float g_rownp[KT64][BATCH * HW];
__device__ float g_rown[BATCH * HW];
__device__ float g_coln[HW];
__device__ float g_top3[BATCH * JSPLIT * HW * 3];

__device__ __forceinline__ void ins3(float &a0, float &a1, float &a2, float x)
{
    float o0 = fminf(a0, x);
    float o1 = fminf(a1, fmaxf(a0, x));
    float o2 = fminf(a2, fmaxf(a1, x));
    a0 = o0; a1 = o1; a2 = o2;
}

__device__ __forceinline__ uint32_t smem_u32(const void* p)
{
    uint32_t a;
    asm("{ .reg .u64 t; cvta.to.shared.u64 t, %1; cvt.u32.u64 %0, t; }"
        : "=r"(a) : "l"(p));
    return a;
}

__device__ __forceinline__ void ldsm4(uint32_t &r0, uint32_t &r1, uint32_t &r2,
                                      uint32_t &r3, uint32_t addr)
{
    asm volatile("ldmatrix.sync.aligned.m8n8.x4.shared.b16 {%0,%1,%2,%3}, [%4];"
                 : "=r"(r0), "=r"(r1), "=r"(r2), "=r"(r3) : "r"(addr));
}

__device__ __forceinline__ void mma16816(float c[4],
                                         uint32_t a0, uint32_t a1, uint32_t a2, uint32_t a3,
                                         uint32_t b0, uint32_t b1)
{
    asm volatile("mma.sync.aligned.m16n8k16.row.col.f32.bf16.bf16.f32 "
                 "{%0,%1,%2,%3}, {%4,%5,%6,%7}, {%8,%9}, {%0,%1,%2,%3};"
                 : "+f"(c[0]), "+f"(c[1]), "+f"(c[2]), "+f"(c[3])
                 : "r"(a0), "r"(a1), "r"(a2), "r"(a3), "r"(b0), "r"(b1));
}

__device__ __forceinline__ void cpa16(uint32_t dst, const void* src, int srcBytes)
{
    asm volatile("cp.async.cg.shared.global [%0], [%1], 16, %2;"
                 :: "r"(dst), "l"(src), "r"(srcBytes));
}
__device__ __forceinline__ void cpa_commit()
{
    asm volatile("cp.async.commit_group;");
}
template<int N> __device__ __forceinline__ void cpa_wait()
{
    asm volatile("cp.async.wait_group %0;" :: "n"(N));
}

// ============================================================================
// fp32 (P, R, S) -> bf16 (P, S, R) tiled transpose+convert
// ============================================================================
__global__ void transpose_conv(const float* __restrict__ in,
                               __nv_bfloat16* __restrict__ out, int R, int S)
{
    __shared__ float tile[32][33];
    int p = blockIdx.z;
    int s0 = blockIdx.x * 32, r0 = blockIdx.y * 32;
    const float* ip = in + (size_t)p * R * S;
    __nv_bfloat16* op = out + (size_t)p * R * S;
    int tx = threadIdx.x, ty = threadIdx.y;
#pragma unroll
    for (int dy = 0; dy < 32; dy += 8) {
        int r = r0 + ty + dy, s = s0 + tx;
        tile[ty + dy][tx] = (r < R && s < S) ? ip[(size_t)r * S + s] : 0.f;
    }
    __syncthreads();
#pragma unroll
    for (int dy = 0; dy < 32; dy += 8) {
        int s = s0 + ty + dy, r = r0 + tx;
        if (s < S && r < R) op[(size_t)s * R + r] = __float2bfloat16(tile[tx][ty + dy]);
    }
}

__global__ void conv_w(const float* __restrict__ W, __nv_bfloat16* __restrict__ Wb)
{
    int i = blockIdx.x * 256 + threadIdx.x;
    if (i >= CH * CH) return;
    int o = i / CH, c = i % CH;
    Wb[i] = __float2bfloat16(W[(size_t)o * WCOLS + c]);
}

// ============================================================================
// bf16 HMMA level GEMM: BK=64, 3-stage cp.async ring, ONE sync per chunk,
// SW128-swizzled 128-B rows, 2 CTAs/SM.
// ============================================================================
#define L6STG  32768u
#define L6B    16384u
#define L6SMEM (3 * 32768)

__global__ __launch_bounds__(256, 2)
void level_mma2(const __nv_bfloat16* __restrict__ Xt,
                __nv_bfloat16* __restrict__ Y, int K, int Nloc, int woff)
{
    extern __shared__ __align__(128) char lsm[];
    const uint32_t smb = smem_u32(lsm);

    const int n0 = blockIdx.x * 128;
    const int m0 = blockIdx.y * 128;
    const int b  = blockIdx.z;
    const __nv_bfloat16* Xb = Xt + (size_t)b * Nloc * K;

    const int tid = threadIdx.x;
    const int lane = tid & 31, w = tid >> 5;
    const int wr = w >> 2, wc = w & 3;
    const int g = lane >> 2, tg = lane & 3;

    const int lr = tid >> 1, lv = tid & 1;
    const __nv_bfloat16* aRow = g_Wb + (size_t)(m0 + lr) * CH + woff + lv * 32;
    const int jB = n0 + lr;
    const __nv_bfloat16* bRow =
        Xb + (size_t)(jB < Nloc ? jB : Nloc - 1) * K + lv * 32;
    const int bvld = (jB < Nloc) ? 16 : 0;
    uint32_t wsw[4];
#pragma unroll
    for (int c = 0; c < 4; c++)
        wsw[c] = (uint32_t)((lv * 64 + c * 16) ^ ((lr & 7) << 4));
    const uint32_t aWrRow = smb + (uint32_t)(lr * 128);
    const uint32_t bWrRow = smb + L6B + (uint32_t)(lr * 128);

    uint32_t aswc[4], bswc[4];
#pragma unroll
    for (int s = 0; s < 4; s++) {
        aswc[s] = (uint32_t)((((lane >> 4) * 16) + s * 32) ^ ((lane & 7) << 4));
        bswc[s] = (uint32_t)(((((lane >> 3) & 1) * 16) + s * 32) ^ ((lane & 7) << 4));
    }
    const uint32_t aRowBase = smb + (uint32_t)(((wr * 64) + (lane & 15)) * 128);
    const uint32_t bRowBase = smb + L6B +
        (uint32_t)((wc * 32 + (lane & 7) + ((lane >> 4) & 1) * 8) * 128);

    float acc[4][4][4];
#pragma unroll
    for (int mi = 0; mi < 4; mi++)
#pragma unroll
        for (int ni = 0; ni < 4; ni++)
#pragma unroll
            for (int q = 0; q < 4; q++) acc[mi][ni][q] = 0.f;

    const int KT = K / 64;
#pragma unroll
    for (int p = 0; p < 2; p++) {
#pragma unroll
        for (int c = 0; c < 4; c++) {
            cpa16(aWrRow + p * L6STG + wsw[c], aRow + p * 64 + c * 8, 16);
            cpa16(bWrRow + p * L6STG + wsw[c], bRow + p * 64 + c * 8, bvld);
        }
        cpa_commit();
    }

    for (int kc = 0; kc < KT; kc++) {
        if (kc < KT - 1) cpa_wait<1>(); else cpa_wait<0>();
        __syncthreads();
        const int kl = kc + 2;
        if (kl < KT) {
            const uint32_t so = (uint32_t)(kl % 3) * L6STG;
#pragma unroll
            for (int c = 0; c < 4; c++) {
                cpa16(aWrRow + so + wsw[c], aRow + kl * 64 + c * 8, 16);
                cpa16(bWrRow + so + wsw[c], bRow + kl * 64 + c * 8, bvld);
            }
            cpa_commit();
        }
        const uint32_t stg = (uint32_t)(kc % 3) * L6STG;
#pragma unroll
        for (int s = 0; s < 4; s++) {
            uint32_t bq[8];
            ldsm4(bq[0], bq[1], bq[2], bq[3], bRowBase + stg + bswc[s]);
            ldsm4(bq[4], bq[5], bq[6], bq[7], bRowBase + stg + 16 * 128 + bswc[s]);
#pragma unroll
            for (int mi = 0; mi < 4; mi++) {
                uint32_t a0, a1, a2, a3;
                ldsm4(a0, a1, a2, a3, aRowBase + stg + mi * 16 * 128 + aswc[s]);
#pragma unroll
                for (int ni = 0; ni < 4; ni++)
                    mma16816(acc[mi][ni], a0, a1, a2, a3, bq[ni * 2], bq[ni * 2 + 1]);
            }
        }
    }

    __nv_bfloat16* Yb = Y + (size_t)b * CH * Nloc;
#pragma unroll
    for (int mi = 0; mi < 4; mi++) {
        int r = m0 + wr * 64 + mi * 16 + g;
#pragma unroll
        for (int ni = 0; ni < 4; ni++) {
            int ccol = n0 + wc * 32 + ni * 8 + 2 * tg;
            if (ccol < Nloc) {
                *reinterpret_cast<__nv_bfloat162*>(&Yb[(size_t)r * Nloc + ccol]) =
                    __floats2bfloat162_rn(acc[mi][ni][0], acc[mi][ni][1]);
                *reinterpret_cast<__nv_bfloat162*>(&Yb[(size_t)(r + 8) * Nloc + ccol]) =
                    __floats2bfloat162_rn(acc[mi][ni][2], acc[mi][ni][3]);
            }
        }
    }
}

// ============================================================================
// Vectorized 3x3 avg pool (zero pad, /9): 4 outputs/thread via bf16x2 loads.
// ============================================================================
template<int S>
__global__ void pool4(const __nv_bfloat16* __restrict__ in,
                      __nv_bfloat16* __restrict__ out, int total4)
{
    constexpr int G = S / 4;
    int idx = blockIdx.x * blockDim.x + threadIdx.x;
    if (idx >= total4) return;
    int gw = idx % G;
    int h  = (idx / G) % S;
    int plane = idx / (G * S);
    int w0 = gw * 4;
    const __nv_bfloat16* ip = in + (size_t)plane * S * S;

    float cs0 = 0.f, cs1 = 0.f, cs2 = 0.f, cs3 = 0.f, cs4 = 0.f, cs5 = 0.f;
#pragma unroll
    for (int dh = -1; dh <= 1; dh++) {
        int hh = h + dh;
        if (hh < 0 || hh >= S) continue;
        const __nv_bfloat16* rp = ip + hh * S;
        if (w0 > 0) {
            __nv_bfloat162 a = *reinterpret_cast<const __nv_bfloat162*>(rp + w0 - 2);
            cs0 += __bfloat162float(a.y);
        }
        __nv_bfloat162 bvv = *reinterpret_cast<const __nv_bfloat162*>(rp + w0);
        cs1 += __bfloat162float(bvv.x);
        cs2 += __bfloat162float(bvv.y);
        __nv_bfloat162 cvv = *reinterpret_cast<const __nv_bfloat162*>(rp + w0 + 2);
        cs3 += __bfloat162float(cvv.x);
        cs4 += __bfloat162float(cvv.y);
        if (w0 + 4 < S) {
            __nv_bfloat162 dvv = *reinterpret_cast<const __nv_bfloat162*>(rp + w0 + 4);
            cs5 += __bfloat162float(dvv.x);
        }
    }
    const float inv9 = 1.f / 9.f;
    float o0 = (cs0 + cs1 + cs2) * inv9;
    float o1 = (cs1 + cs2 + cs3) * inv9;
    float o2 = (cs2 + cs3 + cs4) * inv9;
    float o3 = (cs3 + cs4 + cs5) * inv9;
    __nv_bfloat162 v0 = __floats2bfloat162_rn(o0, o1);
    __nv_bfloat162 v1 = __floats2bfloat162_rn(o2, o3);
    uint2 pk = make_uint2(*reinterpret_cast<uint32_t*>(&v0),
                          *reinterpret_cast<uint32_t*>(&v1));
    *reinterpret_cast<uint2*>(out + (size_t)plane * S * S + h * S + w0) = pk;
}

// scalar pool for S=14
template<int S>
__global__ void pool3b(const __nv_bfloat16* __restrict__ in,
                       __nv_bfloat16* __restrict__ out, int total)
{
    int idx = blockIdx.x * blockDim.x + threadIdx.x;
    if (idx >= total) return;
    int w = idx % S;
    int h = (idx / S) % S;
    const __nv_bfloat16* ip = in + (idx - h * S - w);
    float s = 0.f;
#pragma unroll
    for (int dh = -1; dh <= 1; dh++) {
        int hh = h + dh;
        if (hh < 0 || hh >= S) continue;
#pragma unroll
        for (int dw = -1; dw <= 1; dw++) {
            int ww = w + dw;
            if (ww < 0 || ww >= S) continue;
            s += __bfloat162float(ip[hh * S + ww]);
        }
    }
    out[idx] = __float2bfloat16(s * (1.f / 9.f));
}

// ============================================================================
// Fused assemble -> bf16 phiT (b, i, k) + row-norm partials (batch group)
// ============================================================================
__global__ __launch_bounds__(256)
void assemble_t(const float* __restrict__ Wmat, const float* __restrict__ bvec,
                int b0)
{
    __shared__ float tile[64][65];
    __shared__ float rsum[4][64];
    const int i0 = blockIdx.x * 64;
    const int kt = blockIdx.y;
    const int k0 = kt * 64;
    const int b  = b0 + blockIdx.z;
    const int tx = threadIdx.x;
    const int ty = threadIdx.y;
    const int i  = i0 + tx;
    const int h = i / 56, w = i % 56;

    float w2[4]; int o2[4];
    {
        float cy = (h + 0.5f) * 0.5f - 0.5f;
        float cx = (w + 0.5f) * 0.5f - 0.5f;
        float fy0 = floorf(cy), fx0 = floorf(cx);
        float fy = cy - fy0, fx = cx - fx0;
        int y0 = max((int)fy0, 0), y1 = min((int)fy0 + 1, 27);
        int x0 = max((int)fx0, 0), x1 = min((int)fx0 + 1, 27);
        o2[0] = y0 * 28 + x0; o2[1] = y0 * 28 + x1;
        o2[2] = y1 * 28 + x0; o2[3] = y1 * 28 + x1;
        w2[0] = (1.f - fy) * (1.f - fx); w2[1] = (1.f - fy) * fx;
        w2[2] = fy * (1.f - fx);         w2[3] = fy * fx;
    }
    float w3[4]; int o3[4];
    {
        float cy = (h + 0.5f) * 0.25f - 0.5f;
        float cx = (w + 0.5f) * 0.25f - 0.5f;
        float fy0 = floorf(cy), fx0 = floorf(cx);
        float fy = cy - fy0, fx = cx - fx0;
        int y0 = max((int)fy0, 0), y1 = min((int)fy0 + 1, 13);
        int x0 = max((int)fx0, 0), x1 = min((int)fx0 + 1, 13);
        o3[0] = y0 * 14 + x0; o3[1] = y0 * 14 + x1;
        o3[2] = y1 * 14 + x0; o3[3] = y1 * 14 + x1;
        w3[0] = (1.f - fy) * (1.f - fx); w3[1] = (1.f - fy) * fx;
        w3[2] = fy * (1.f - fx);         w3[3] = fy * fx;
    }
    const float xx = fmaf(2.f / 55.f, (float)w, -1.f);
    const float yy = fmaf(2.f / 55.f, (float)h, -1.f);

    float s = 0.f;
    for (int r = ty; r < 64; r += 4) {
        const int k = k0 + r;
        const size_t pk = (size_t)b * CH + k;
        float v = __bfloat162float(g_q1[pk * 3136 + i]);
        const __nv_bfloat16* pl2 = g_q2 + pk * 784;
        const __nv_bfloat16* pl3 = g_q3 + pk * 196;
        v += w2[0] * __bfloat162float(pl2[o2[0]]) + w2[1] * __bfloat162float(pl2[o2[1]])
           + w2[2] * __bfloat162float(pl2[o2[2]]) + w2[3] * __bfloat162float(pl2[o2[3]]);
        v += w3[0] * __bfloat162float(pl3[o3[0]]) + w3[1] * __bfloat162float(pl3[o3[1]])
           + w3[2] * __bfloat162float(pl3[o3[2]]) + w3[3] * __bfloat162float(pl3[o3[3]]);
        v += Wmat[(size_t)k * WCOLS + 1792] * xx
           + Wmat[(size_t)k * WCOLS + 1793] * yy
           + bvec[k];
        float fq = __bfloat162float(__float2bfloat16(v));
        tile[r][tx] = fq;
        s = fmaf(fq, fq, s);
    }
    rsum[ty][tx] = s;
    __syncthreads();
    if (ty == 0)
        g_rownp[kt][b * HW + i] = rsum[0][tx] + rsum[1][tx] + rsum[2][tx] + rsum[3][tx];
#pragma unroll
    for (int q = 0; q < 16; q++) {
        int ri = ty + q * 4;
        g_phiT[((size_t)b * HW + (i0 + ri)) * CH + k0 + tx] =
            __float2bfloat16(tile[tx][ri]);
    }
}

__global__ void reduce_rown(int b0)
{
    int idx = blockIdx.x * 256 + threadIdx.x;
    if (idx >= HB * HW) return;
    idx += b0 * HW;
    float s = 0.f;
#pragma unroll
    for (int q = 0; q < KT64; q++) s += g_rownp[q][idx];
    g_rown[idx] = s;
}

__global__ void col_norms_b()
{
    int gw = (blockIdx.x * 256 + threadIdx.x) >> 5;
    int lane = threadIdx.x & 31;
    if (gw >= HW) return;
    const __nv_bfloat16* row = g_Ct + (size_t)gw * CH;
    float s = 0.f;
    for (int k = lane; k < CH; k += 32) {
        float v = __bfloat162float(row[k]);
        s = fmaf(v, v, s);
    }
#pragma unroll
    for (int m = 16; m; m >>= 1) s += __shfl_xor_sync(0xffffffffu, s, m);
    if (lane == 0) g_coln[gw] = s;
}

// ============================================================================
// Fused distance GEMM (HMMA, 128x128, 256 thr, 8 warps 2x4, warp tile 64x32):
// BK=64, 3-stage cp.async ring, ONE __syncthreads per 64-k chunk,
// SW128-swizzled 128-B smem rows, 2 CTAs/SM. Grid (25, HB, JSPLIT).
// ============================================================================
#define D6STG  32768u
#define D6B    16384u
#define D6RED  (3 * 32768)
#define D6SMEM (D6RED + 4 * 128 * 3 * 4)

__global__ __launch_bounds__(256, 2)
void dist_mma6(int b0)
{
    extern __shared__ __align__(128) char dsm[];
    const uint32_t smb = smem_u32(dsm);
    float* red = reinterpret_cast<float*>(dsm + D6RED);

    const int tid = threadIdx.x;
    const int lane = tid & 31, w = tid >> 5;
    const int wr = w >> 2, wc = w & 3;
    const int g = lane >> 2, tg = lane & 3;
    const int m0 = blockIdx.x * 128;
    const int b  = b0 + blockIdx.y;
    const int js = blockIdx.z;
    const int jt0 = (js * 25) / JSPLIT;
    const int jt1 = ((js + 1) * 25) / JSPLIT;

    const int lr = tid >> 1, lv = tid & 1;
    const int iA = m0 + lr;
    const __nv_bfloat16* aRow =
        g_phiT + ((size_t)b * HW + (iA < HW ? iA : HW - 1)) * CH + lv * 32;
    const int avld = (iA < HW) ? 16 : 0;
    uint32_t wsw[4];
#pragma unroll
    for (int c = 0; c < 4; c++)
        wsw[c] = (uint32_t)((lv * 64 + c * 16) ^ ((lr & 7) << 4));
    const uint32_t aWrRow = smb + (uint32_t)(lr * 128);
    const uint32_t bWrRow = smb + D6B + (uint32_t)(lr * 128);

    uint32_t aswc[4], bswc[4];
#pragma unroll
    for (int s = 0; s < 4; s++) {
        aswc[s] = (uint32_t)((((lane >> 4) * 16) + s * 32) ^ ((lane & 7) << 4));
        bswc[s] = (uint32_t)(((((lane >> 3) & 1) * 16) + s * 32) ^ ((lane & 7) << 4));
    }
    const uint32_t aRowBase = smb + (uint32_t)(((wr * 64) + (lane & 15)) * 128);
    const uint32_t bRowBase = smb + D6B +
        (uint32_t)((wc * 32 + (lane & 7) + ((lane >> 4) & 1) * 8) * 128);

    float nr[4][2];
    float t0[4][2], t1[4][2], t2[4][2];
#pragma unroll
    for (int mi = 0; mi < 4; mi++)
#pragma unroll
        for (int hh = 0; hh < 2; hh++) {
            int r = m0 + wr * 64 + mi * 16 + g + hh * 8;
            nr[mi][hh] = (r < HW) ? g_rown[b * HW + r] : 0.f;
            t0[mi][hh] = INFINITY; t1[mi][hh] = INFINITY; t2[mi][hh] = INFINITY;
        }

    for (int jt = jt0; jt < jt1; jt++) {
        const int n0 = jt * 128;
        const __nv_bfloat16* bRow = g_Ct + (size_t)(n0 + lr) * CH + lv * 32;

        float acc[4][4][4];
#pragma unroll
        for (int mi = 0; mi < 4; mi++)
#pragma unroll
            for (int ni = 0; ni < 4; ni++)
#pragma unroll
                for (int q = 0; q < 4; q++) acc[mi][ni][q] = 0.f;

        __syncthreads();
#pragma unroll
        for (int p = 0; p < 2; p++) {
#pragma unroll
            for (int c = 0; c < 4; c++) {
                cpa16(aWrRow + p * D6STG + wsw[c], aRow + p * 64 + c * 8, avld);
                cpa16(bWrRow + p * D6STG + wsw[c], bRow + p * 64 + c * 8, 16);
            }
            cpa_commit();
        }

        for (int kc = 0; kc < KT64; kc++) {
            if (kc < KT64 - 1) cpa_wait<1>(); else cpa_wait<0>();
            __syncthreads();
            const int kl = kc + 2;
            if (kl < KT64) {
                const uint32_t so = (uint32_t)(kl % 3) * D6STG;
#pragma unroll
                for (int c = 0; c < 4; c++) {
                    cpa16(aWrRow + so + wsw[c], aRow + kl * 64 + c * 8, avld);
                    cpa16(bWrRow + so + wsw[c], bRow + kl * 64 + c * 8, 16);
                }
                cpa_commit();
            }
            const uint32_t stg = (uint32_t)(kc % 3) * D6STG;
#pragma unroll
            for (int s = 0; s < 4; s++) {
                uint32_t bq[8];
                ldsm4(bq[0], bq[1], bq[2], bq[3], bRowBase + stg + bswc[s]);
                ldsm4(bq[4], bq[5], bq[6], bq[7], bRowBase + stg + 16 * 128 + bswc[s]);
#pragma unroll
                for (int mi = 0; mi < 4; mi++) {
                    uint32_t a0, a1, a2, a3;
                    ldsm4(a0, a1, a2, a3, aRowBase + stg + mi * 16 * 128 + aswc[s]);
#pragma unroll
                    for (int ni = 0; ni < 4; ni++)
                        mma16816(acc[mi][ni], a0, a1, a2, a3, bq[ni * 2], bq[ni * 2 + 1]);
                }
            }
        }

#pragma unroll
        for (int ni = 0; ni < 4; ni++) {
            int col0 = n0 + wc * 32 + ni * 8 + 2 * tg;
            if (col0 < HW) {
                float mj0 = g_coln[col0];
                float mj1 = g_coln[col0 + 1];
#pragma unroll
                for (int mi = 0; mi < 4; mi++) {
#pragma unroll
                    for (int hh = 0; hh < 2; hh++) {
                        float base = nr[mi][hh];
                        float d0 = fmaf(-2.f, acc[mi][ni][hh * 2],     base + mj0);
                        float d1 = fmaf(-2.f, acc[mi][ni][hh * 2 + 1], base + mj1);
                        ins3(t0[mi][hh], t1[mi][hh], t2[mi][hh], d0);
                        ins3(t0[mi][hh], t1[mi][hh], t2[mi][hh], d1);
                    }
                }
            }
        }
    }

#pragma unroll
    for (int msk = 1; msk < 4; msk <<= 1) {
#pragma unroll
        for (int mi = 0; mi < 4; mi++)
#pragma unroll
            for (int hh = 0; hh < 2; hh++) {
                float b0s = __shfl_xor_sync(0xffffffffu, t0[mi][hh], msk);
                float b1s = __shfl_xor_sync(0xffffffffu, t1[mi][hh], msk);
                float b2s = __shfl_xor_sync(0xffffffffu, t2[mi][hh], msk);
                ins3(t0[mi][hh], t1[mi][hh], t2[mi][hh], b0s);
                ins3(t0[mi][hh], t1[mi][hh], t2[mi][hh], b1s);
                ins3(t0[mi][hh], t1[mi][hh], t2[mi][hh], b2s);
            }
    }
    __syncthreads();
    if (tg == 0) {
#pragma unroll
        for (int mi = 0; mi < 4; mi++)
#pragma unroll
            for (int hh = 0; hh < 2; hh++) {
                int rl = wr * 64 + mi * 16 + g + hh * 8;
                float* rp = red + (wc * 128 + rl) * 3;
                rp[0] = t0[mi][hh];
                rp[1] = t1[mi][hh];
                rp[2] = t2[mi][hh];
            }
    }
    __syncthreads();
    if (tid < 128) {
        int ig = m0 + tid;
        if (ig < HW) {
            float a0 = INFINITY, a1 = INFINITY, a2 = INFINITY;
#pragma unroll
            for (int wcx = 0; wcx < 4; wcx++) {
                const float* rp = red + (wcx * 128 + tid) * 3;
                ins3(a0, a1, a2, rp[0]);
                ins3(a0, a1, a2, rp[1]);
                ins3(a0, a1, a2, rp[2]);
            }
            size_t base = (((size_t)b * JSPLIT + js) * HW + ig) * 3;
            g_top3[base + 0] = a0;
            g_top3[base + 1] = a1;
            g_top3[base + 2] = a2;
        }
    }
}

__global__ void finalize(float* __restrict__ out)
{
    int idx = blockIdx.x * blockDim.x + threadIdx.x;
    if (idx >= BATCH * HW) return;
    int b = idx / HW;
    int i = idx % HW;
    float t0 = INFINITY, t1 = INFINITY, t2 = INFINITY;
#pragma unroll
    for (int js = 0; js < JSPLIT; js++) {
        size_t base = (((size_t)b * JSPLIT + js) * HW + i) * 3;
        ins3(t0, t1, t2, g_top3[base + 0]);
        ins3(t0, t1, t2, g_top3[base + 1]);
        ins3(t0, t1, t2, g_top3[base + 2]);
    }
    float d0 = sqrtf(fmaxf(t0, 0.f));
    float d1 = sqrtf(fmaxf(t1, 0.f));
    float d2 = sqrtf(fmaxf(t2, 0.f));
    float w0 = 1.f / (1.f + expf(d0 - d1) + expf(d0 - d2));
    out[idx] = w0 * d0;
}

// ============================================================================
extern "C" void kernel_launch(void* const* d_in, const int* in_sizes, int n_in,
                              void* d_out, int out_size)
{
    const float *p1 = nullptr, *p2 = nullptr, *p3 = nullptr;
    const float *W = nullptr, *bv = nullptr, *Cm = nullptr;
    for (int i = 0; i < n_in; i++) {
        switch (in_sizes[i]) {
            case 8 * 256 * 56 * 56:  p1 = (const float*)d_in[i]; break;
            case 8 * 512 * 28 * 28:  p2 = (const float*)d_in[i]; break;
            case 8 * 1024 * 14 * 14: p3 = (const float*)d_in[i]; break;
            case 1792 * 1794:        W  = (const float*)d_in[i]; break;
            case 1792:               bv = (const float*)d_in[i]; break;
            case 1792 * 3136:        Cm = (const float*)d_in[i]; break;
            default: break;
        }
    }

    void *wb, *x1t, *x2t, *x3t, *ct;
    void *y1, *y2, *y3, *q1, *q2, *q3;
    cudaGetSymbolAddress(&wb,  g_Wb);
    cudaGetSymbolAddress(&x1t, g_x1t);
    cudaGetSymbolAddress(&x2t, g_x2t);
    cudaGetSymbolAddress(&x3t, g_x3t);
    cudaGetSymbolAddress(&ct,  g_Ct);
    cudaGetSymbolAddress(&y1,  g_y1);  cudaGetSymbolAddress(&q1, g_q1);
    cudaGetSymbolAddress(&y2,  g_y2);  cudaGetSymbolAddress(&q2, g_q2);
    cudaGetSymbolAddress(&y3,  g_y3);  cudaGetSymbolAddress(&q3, g_q3);

    // one-time host-side resources (no device memory involved)
    static cudaStream_t s1 = nullptr, s2 = nullptr, s3 = nullptr;
    static cudaEvent_t eF, e0, e1, e2, e3, eM, eA, eG1, eT1;
    if (!s1) {
        cudaStreamCreateWithFlags(&s1, cudaStreamNonBlocking);
        cudaStreamCreateWithFlags(&s2, cudaStreamNonBlocking);
        cudaStreamCreateWithFlags(&s3, cudaStreamNonBlocking);
        cudaEventCreateWithFlags(&eF,  cudaEventDisableTiming);
        cudaEventCreateWithFlags(&e0,  cudaEventDisableTiming);
        cudaEventCreateWithFlags(&e1,  cudaEventDisableTiming);
        cudaEventCreateWithFlags(&e2,  cudaEventDisableTiming);
        cudaEventCreateWithFlags(&e3,  cudaEventDisableTiming);
        cudaEventCreateWithFlags(&eM,  cudaEventDisableTiming);
        cudaEventCreateWithFlags(&eA,  cudaEventDisableTiming);
        cudaEventCreateWithFlags(&eG1, cudaEventDisableTiming);
        cudaEventCreateWithFlags(&eT1, cudaEventDisableTiming);
        cudaFuncSetAttribute(dist_mma6,
                             cudaFuncAttributeMaxDynamicSharedMemorySize, D6SMEM);
        cudaFuncSetAttribute(level_mma2,
                             cudaFuncAttributeMaxDynamicSharedMemorySize, L6SMEM);
    }

    dim3 tb(32, 8);

    // fork event FIRST (capture legality), then independent transposes
    cudaEventRecord(eF, 0);
    cudaStreamWaitEvent(s1, eF, 0);
    cudaStreamWaitEvent(s2, eF, 0);
    cudaStreamWaitEvent(s3, eF, 0);

    // t1 on s2 overlaps conv_w on main (t1 doesn't need Wb)
    transpose_conv<<<dim3(98, 8, 8), tb, 0, s2>>>(p1, (__nv_bfloat16*)x1t, 256, 3136);
    cudaEventRecord(eT1, s2);

    transpose_conv<<<dim3(25, 16, 8), tb, 0, s1>>>(p2, (__nv_bfloat16*)x2t, 512, 784);
    transpose_conv<<<dim3(7, 32, 8), tb, 0, s2>>>(p3, (__nv_bfloat16*)x3t, 1024, 196);
    transpose_conv<<<dim3(98, 56, 1), tb, 0, s3>>>(Cm, (__nv_bfloat16*)ct, 1792, 3136);
    col_norms_b<<<(HW * 32 + 255) / 256, 256, 0, s3>>>();
    cudaEventRecord(e3, s3);

    // main: Wb conversion (gates the level GEMMs), then level-1 chain
    conv_w<<<(CH * CH + 255) / 256, 256>>>(W, (__nv_bfloat16*)wb);
    cudaEventRecord(e0, 0);
    cudaStreamWaitEvent(s1, e0, 0);
    cudaStreamWaitEvent(s2, e0, 0);

    cudaStreamWaitEvent(0, eT1, 0);
    level_mma2<<<dim3(25, 14, 8), 256, L6SMEM>>>((const __nv_bfloat16*)x1t,
                                                 (__nv_bfloat16*)y1, 256, 3136, 0);
    pool4<56><<<(BATCH * CH * 3136 / 4 + 255) / 256, 256>>>(
        (const __nv_bfloat16*)y1, (__nv_bfloat16*)q1, BATCH * CH * 3136 / 4);
    cudaEventRecord(eM, 0);

    // s1: level-2 chain
    level_mma2<<<dim3(7, 14, 8), 256, L6SMEM, s1>>>((const __nv_bfloat16*)x2t,
                                                    (__nv_bfloat16*)y2, 512, 784, 256);
    pool4<28><<<(BATCH * CH * 784 / 4 + 255) / 256, 256, 0, s1>>>(
        (const __nv_bfloat16*)y2, (__nv_bfloat16*)q2, BATCH * CH * 784 / 4);
    cudaEventRecord(e1, s1);

    // s2: level-3 chain
    level_mma2<<<dim3(2, 14, 8), 256, L6SMEM, s2>>>((const __nv_bfloat16*)x3t,
                                                    (__nv_bfloat16*)y3, 1024, 196, 768);
    pool3b<14><<<(BATCH * CH * 196 + 255) / 256, 256, 0, s2>>>(
        (const __nv_bfloat16*)y3, (__nv_bfloat16*)q3, BATCH * CH * 196);
    cudaEventRecord(e2, s2);

    // ---- group 0 (batches 0..3) on main; group 1 (4..7) on s1, staggered ----
    cudaStreamWaitEvent(0, e1, 0);
    cudaStreamWaitEvent(0, e2, 0);
    cudaStreamWaitEvent(0, e3, 0);

    assemble_t<<<dim3(49, 28, HB), dim3(64, 4)>>>(W, bv, 0);
    reduce_rown<<<(HB * HW + 255) / 256, 256>>>(0);
    cudaEventRecord(eA, 0);

    // s1 runs group 1 after group 0's assemble (overlaps with dist_g0)
    cudaStreamWaitEvent(s1, eM, 0);
    cudaStreamWaitEvent(s1, e2, 0);
    cudaStreamWaitEvent(s1, e3, 0);
    cudaStreamWaitEvent(s1, eA, 0);
    assemble_t<<<dim3(49, 28, HB), dim3(64, 4), 0, s1>>>(W, bv, HB);
    reduce_rown<<<(HB * HW + 255) / 256, 256, 0, s1>>>(HB);
    dist_mma6<<<dim3(25, HB, JSPLIT), 256, D6SMEM, s1>>>(HB);
    cudaEventRecord(eG1, s1);

    dist_mma6<<<dim3(25, HB, JSPLIT), 256, D6SMEM>>>(0);

    cudaStreamWaitEvent(0, eG1, 0);
    finalize<<<(BATCH * HW + 255) / 256, 256>>>((float*)d_out);
}